// round 7
// baseline (speedup 1.0000x reference)
#include <cuda_runtime.h>
#include <math.h>
#include <stdint.h>

#define BATCH 16
#define H 1024
#define W 1024
#define HW (H * W)
#define CAP 262144
#define NSAMP 65536
#define TWO_PI_F 6.28318530717958647692f
#define STEP_F 0.78539816339744830962f
#define EPSV 1e-6f

// global 0-based ranks: floor/ceil element of quantile positions 20971.5 and 1027603.5
__constant__ int c_ranks[4] = {20971, 20972, 1027603, 1027604};
// sample-rank walk targets (NSAMP=65536): p*ns = 1310.7 / 64225.3, margin 342 (10 sigma)
__constant__ int c_wrank[4] = {968, 1653, 63883, 64567};

// ---------------- device scratch ----------------
__device__ unsigned g_cnt[BATCH][2];
__device__ unsigned g_below[BATCH][2];
__device__ unsigned g_cand[BATCH][2][CAP];
__device__ float    g_rlo[BATCH][2];
__device__ float    g_rhi[BATCH][2];
__device__ int      g_snt[BATCH][2];
__device__ int      g_grank[BATCH][2][4];
__device__ int      g_stid[BATCH][2][4];
__device__ int      g_fail[BATCH];
__device__ float    g_qval[BATCH][4];

__constant__ int c_dy[8] = {0, -1, -1, -1, 0, 1, 1, 1};
__constant__ int c_dx[8] = {1, 1, 0, -1, -1, -1, 0, 1};

__device__ __forceinline__ unsigned f2key(float f) {
    unsigned u = __float_as_uint(f);
    return (u & 0x80000000u) ? ~u : (u | 0x80000000u);
}
__device__ __forceinline__ float key2f(unsigned k) {
    unsigned u = (k & 0x80000000u) ? (k & 0x7fffffffu) : ~k;
    return __uint_as_float(u);
}
__device__ __forceinline__ int sample_idx(int i) {
    int chunk = i >> 6;                       // 1024 chunks, one per row
    int off = (chunk * 7919) & 960;           // 64-aligned pseudo-random offset in row
    return (chunk << 10) + off + (i & 63);
}

// ---------------- warp-parallel histogram walk (full-mask shuffles only) ----------------
__device__ __forceinline__ int warp_walk(const unsigned* hist, int nb, int& rank) {
    int lane = threadIdx.x & 31;
    int chunk = nb / 32;
    const unsigned* hc = hist + lane * chunk;
    unsigned s = 0;
    for (int j = 0; j < chunk; j++) s += hc[j];
    unsigned inc = s;
#pragma unroll
    for (int o = 1; o < 32; o <<= 1) {
        unsigned v = __shfl_up_sync(0xffffffffu, inc, o);
        if (lane >= o) inc += v;
    }
    unsigned ex = inc - s;
    unsigned ball = __ballot_sync(0xffffffffu, (int)ex <= rank);
    int sel = 31 - __clz(ball);
    int d = 0, r = rank;
    if (lane == sel) {
        r = rank - (int)ex;
        d = lane * chunk;
        for (int j = 0; j < chunk; j++) {
            unsigned c = hc[j];
            if (r < (int)c) { d = lane * chunk + j; break; }
            r -= (int)c;
        }
    }
    d = __shfl_sync(0xffffffffu, d, sel);
    r = __shfl_sync(0xffffffffu, r, sel);
    rank = r;
    return d;
}

// ---------------- sampled bounds: value-space binning, one block per batch ----------------
__global__ __launch_bounds__(1024) void k_bounds(const float* __restrict__ x) {
    __shared__ unsigned h[8192];
    __shared__ float red[64];
    __shared__ int sb[4];
    __shared__ float s_mn, s_scale;
    int b = blockIdx.x;
    const float* xb = x + (size_t)b * HW;
    int tid = threadIdx.x;

    // pass 1: min/max of samples
    float mn = __int_as_float(0x7f800000), mx = -mn;
    for (int i = tid; i < NSAMP; i += 1024) {
        float v = xb[sample_idx(i)];
        mn = fminf(mn, v); mx = fmaxf(mx, v);
    }
#pragma unroll
    for (int o = 16; o > 0; o >>= 1) {
        mn = fminf(mn, __shfl_down_sync(0xffffffffu, mn, o));
        mx = fmaxf(mx, __shfl_down_sync(0xffffffffu, mx, o));
    }
    int w = tid >> 5;
    if ((tid & 31) == 0) { red[w] = mn; red[32 + w] = mx; }
    __syncthreads();
    if (tid == 0) {
        float m0 = red[0], m1 = red[32];
        for (int i = 1; i < 32; i++) { m0 = fminf(m0, red[i]); m1 = fmaxf(m1, red[32 + i]); }
        s_mn = m0;
        s_scale = 8192.0f / fmaxf(m1 - m0, 1e-30f);
    }
    for (int i = tid; i < 8192; i += 1024) h[i] = 0u;
    __syncthreads();
    float smn = s_mn, sscale = s_scale;
    float binw = 1.0f / sscale;

    // pass 2: value-binned histogram (uniform data -> ~8/bin, no contention)
    for (int i = tid; i < NSAMP; i += 1024) {
        float v = xb[sample_idx(i)];
        int bin = (int)((v - smn) * sscale);
        bin = min(max(bin, 0), 8191);
        atomicAdd(&h[bin], 1u);
    }
    __syncthreads();
    if (w < 4) {
        int r = c_wrank[w];
        int d = warp_walk(h, 8192, r);
        if ((tid & 31) == 0) sb[w] = d;
    }
    __syncthreads();
    if (tid == 0) {
        float inf = __int_as_float(0x7f800000);
        bool merged = (sb[2] <= sb[1] + 3);
        int hb0 = merged ? sb[3] : sb[1];
        g_rlo[b][0] = smn + (float)(sb[0] - 1) * binw;
        g_rhi[b][0] = smn + (float)(hb0 + 2) * binw;
        g_cnt[b][0] = 0u; g_cnt[b][1] = 0u;
        g_below[b][0] = 0u; g_below[b][1] = 0u;
        g_fail[b] = 0;
        if (merged) {
            g_snt[b][0] = 4; g_snt[b][1] = 0;
            g_rlo[b][1] = inf; g_rhi[b][1] = inf;
            for (int t = 0; t < 4; t++) { g_stid[b][0][t] = t; g_grank[b][0][t] = c_ranks[t]; }
        } else {
            g_snt[b][0] = 2; g_snt[b][1] = 2;
            g_rlo[b][1] = smn + (float)(sb[2] - 1) * binw;
            g_rhi[b][1] = smn + (float)(sb[3] + 2) * binw;
            for (int t = 0; t < 2; t++) {
                g_stid[b][0][t] = t;     g_grank[b][0][t] = c_ranks[t];
                g_stid[b][1][t] = 2 + t; g_grank[b][1][t] = c_ranks[2 + t];
            }
        }
    }
}

// ---------------- collect candidates + exact below-counts (direct global append) ----------------
__global__ __launch_bounds__(256) void k_collect(const float* __restrict__ x) {
    int b = blockIdx.y;
    float l0 = g_rlo[b][0], h0 = g_rhi[b][0];
    float l1 = g_rlo[b][1], h1 = g_rhi[b][1];
    unsigned below0 = 0, below1 = 0;

    const float4* xb = (const float4*)(x + (size_t)b * HW);
    const int nvec = HW / 4;
    for (int i = blockIdx.x * blockDim.x + threadIdx.x; i < nvec; i += gridDim.x * blockDim.x) {
        float4 v4 = xb[i];
        float vs[4] = {v4.x, v4.y, v4.z, v4.w};
#pragma unroll
        for (int e = 0; e < 4; e++) {
            float v = vs[e];
            below0 += (v < l0);
            below1 += (v < l1);
            if (v >= l0 && v < h0) {
                unsigned gi = atomicAdd(&g_cnt[b][0], 1u);
                if (gi < CAP) g_cand[b][0][gi] = f2key(v);
            } else if (v >= l1 && v < h1) {
                unsigned gi = atomicAdd(&g_cnt[b][1], 1u);
                if (gi < CAP) g_cand[b][1][gi] = f2key(v);
            }
        }
    }
#pragma unroll
    for (int o = 16; o > 0; o >>= 1) {
        below0 += __shfl_down_sync(0xffffffffu, below0, o);
        below1 += __shfl_down_sync(0xffffffffu, below1, o);
    }
    if ((threadIdx.x & 31) == 0) {
        atomicAdd(&g_below[b][0], below0);
        atomicAdd(&g_below[b][1], below1);
    }
}

// ---------------- exact select over relative keys (dynamic shift schedule) ----------------
__global__ void k_select() {
    int b = blockIdx.x >> 1, s = blockIdx.x & 1;
    __shared__ unsigned hT[4][2048];
    __shared__ int s_rank[4];
    __shared__ unsigned s_pref[4];
    __shared__ int s_bad;
    int nt = g_snt[b][s];
    if (nt == 0) return;
    unsigned n = g_cnt[b][s];
    unsigned below = g_below[b][s];
    float fl = g_rlo[b][s], fh = g_rhi[b][s];
    unsigned klo = f2key(fl), khi = f2key(fh);
    if (threadIdx.x == 0) {
        int bad = (n > CAP) || (n == 0) || (khi <= klo);
        for (int t = 0; t < nt; t++) {
            int r = g_grank[b][s][t] - (int)below;
            if (r < 0 || r >= (int)n) bad = 1;
            s_rank[t] = r;
            s_pref[t] = 0u;
        }
        s_bad = bad;
        if (bad) g_fail[b] = 1;
    }
    __syncthreads();
    if (s_bad) return;
    const unsigned* cand = g_cand[b][s];
    int w = threadIdx.x >> 5;

    unsigned relmax = khi - klo - 1u;
    int bw = 32 - __clz(relmax | 1u);
    int sh0 = bw > 11 ? bw - 11 : 0;
    int sh1 = sh0 > 11 ? sh0 - 11 : 0;
    int shifts[3] = {sh0, sh1, 0};
    int prevsh = bw;

#pragma unroll
    for (int lvl = 0; lvl < 3; lvl++) {
        int cs = shifts[lvl];
        int bits = prevsh - cs;
        unsigned mask = (bits >= 32) ? 0xFFFFFFFFu : ((1u << bits) - 1u);
        for (int i = threadIdx.x; i < 4 * 2048; i += blockDim.x) ((unsigned*)hT)[i] = 0u;
        __syncthreads();
        if (lvl == 0) {
            for (unsigned i = threadIdx.x; i < n; i += blockDim.x) {
                unsigned rel = cand[i] - klo;
                atomicAdd(&hT[0][(rel >> cs) & mask], 1u);
            }
        } else {
            unsigned p0 = s_pref[0], p1 = s_pref[1], p2 = s_pref[2], p3 = s_pref[3];
            for (unsigned i = threadIdx.x; i < n; i += blockDim.x) {
                unsigned rel = cand[i] - klo;
                unsigned hib = rel >> prevsh;
                unsigned dig = (rel >> cs) & mask;
                if (hib == p0) atomicAdd(&hT[0][dig], 1u);
                if (nt > 1 && hib == p1) atomicAdd(&hT[1][dig], 1u);
                if (nt > 2 && hib == p2) atomicAdd(&hT[2][dig], 1u);
                if (nt > 3 && hib == p3) atomicAdd(&hT[3][dig], 1u);
            }
        }
        __syncthreads();
        if (w < nt) {
            int r = s_rank[w];
            const unsigned* hh = (lvl == 0) ? &hT[0][0] : &hT[w][0];
            int d = warp_walk(hh, 2048, r);
            if ((threadIdx.x & 31) == 0) {
                s_pref[w] = (s_pref[w] << bits) | (unsigned)d;
                s_rank[w] = r;
            }
        }
        __syncthreads();
        prevsh = cs;
        if (cs == 0) break;
    }
    if (w < nt && (threadIdx.x & 31) == 0) {
        unsigned key = klo + s_pref[w];
        g_qval[b][g_stid[b][s][w]] = key2f(key);
    }
}

// ---------------- rescue: full exact per-batch select (runs only on sampled-bounds miss) ----------------
__global__ void k_rescue(const float* __restrict__ x) {
    int b = blockIdx.x;
    if (!g_fail[b]) return;
    __shared__ unsigned h[8192];
    __shared__ int sbin[4], sd2[4], srnk[4];
    const float* xb = x + (size_t)b * HW;

    for (int i = threadIdx.x; i < 8192; i += blockDim.x) h[i] = 0u;
    __syncthreads();
    for (int i = threadIdx.x; i < HW; i += blockDim.x)
        atomicAdd(&h[f2key(xb[i]) >> 19], 1u);
    __syncthreads();
    int w = threadIdx.x >> 5;
    if (w < 4) {
        int r = c_ranks[w];
        int d = warp_walk(h, 8192, r);
        if ((threadIdx.x & 31) == 0) { sbin[w] = d; srnk[w] = r; }
    }
    __syncthreads();
    for (int t = 0; t < 4; t++) {
        for (int i = threadIdx.x; i < 2048; i += blockDim.x) h[i] = 0u;
        __syncthreads();
        unsigned tb = (unsigned)sbin[t];
        for (int i = threadIdx.x; i < HW; i += blockDim.x) {
            unsigned k = f2key(xb[i]);
            if ((k >> 19) == tb) atomicAdd(&h[(k >> 8) & 2047u], 1u);
        }
        __syncthreads();
        if (w == 0) {
            int r = srnk[t];
            int d = warp_walk(h, 2048, r);
            if ((threadIdx.x & 31) == 0) { sd2[t] = d; srnk[t] = r; }
        }
        __syncthreads();
    }
    for (int t = 0; t < 4; t++) {
        for (int i = threadIdx.x; i < 256; i += blockDim.x) h[i] = 0u;
        __syncthreads();
        unsigned pre = ((unsigned)sbin[t] << 11) | (unsigned)sd2[t];
        for (int i = threadIdx.x; i < HW; i += blockDim.x) {
            unsigned k = f2key(xb[i]);
            if ((k >> 8) == pre) atomicAdd(&h[k & 255u], 1u);
        }
        __syncthreads();
        if (w == 0) {
            int r = srnk[t];
            int d = warp_walk(h, 256, r);
            if ((threadIdx.x & 31) == 0)
                g_qval[b][t] = key2f(((unsigned)sbin[t] << 19) | ((unsigned)sd2[t] << 8) | (unsigned)d);
        }
        __syncthreads();
    }
}

// ---------------- fused: normalize + sobel + atan2 + dir-max + end map (64x64 tiles) ----------------
#define TS 64
#define HALO 6
#define SW (TS + 2 * HALO)   // 76
#define SPITCH (SW + 1)      // 77

__global__ __launch_bounds__(512) void k_fused(const float* __restrict__ x,
                                               float* __restrict__ emap,
                                               float* __restrict__ binsf,
                                               float* __restrict__ xnout) {
    __shared__ float tile[SW * SPITCH];
    int b = blockIdx.z;
    int bx = blockIdx.x * TS, by = blockIdx.y * TS;
    const float* xb = x + (size_t)b * HW;
    int tid = threadIdx.x;

    float q0 = g_qval[b][0], q1 = g_qval[b][1];
    float q2 = g_qval[b][2], q3 = g_qval[b][3];
    float lo = q0 + 0.5f * (q1 - q0);
    float hi = q2 + 0.5f * (q3 - q2);
    float den = hi - lo + EPSV;

    bool interior = (bx >= HALO) && (bx + TS + HALO <= W) && (by >= HALO) && (by + TS + HALO <= H);
    if (interior) {
        const float* src = xb + (size_t)(by - HALO) * W + (bx - HALO);
        for (int i = tid; i < SW * SW; i += 512) {
            int r = i / SW, c = i - r * SW;
            tile[r * SPITCH + c] = fminf(fmaxf((src[r * W + c] - lo) / den, 0.f), 1.f);
        }
    } else {
        for (int i = tid; i < SW * SW; i += 512) {
            int r = i / SW, c = i - r * SW;
            int gy = by + r - HALO, gx = bx + c - HALO;
            float v = 0.f;
            if ((unsigned)gy < H && (unsigned)gx < W)
                v = fminf(fmaxf((xb[gy * W + gx] - lo) / den, 0.f), 1.f);
            tile[r * SPITCH + c] = v;
        }
    }
    __syncthreads();

    int lx = tid & 63;
    int ly0 = tid >> 6;          // 0..7
#pragma unroll
    for (int k = 0; k < 8; k++) {
        int ly = ly0 + k * 8;
        int ty = ly + HALO, tx = lx + HALO;
        const float* t0 = &tile[ty * SPITCH + tx];

        float a00 = t0[-SPITCH - 1], a01 = t0[-SPITCH], a02 = t0[-SPITCH + 1];
        float a10 = t0[-1], a12 = t0[1];
        float a20 = t0[SPITCH - 1], a21 = t0[SPITCH], a22 = t0[SPITCH + 1];
        float gxs = (a02 - a00) + 2.f * (a12 - a10) + (a22 - a20);
        float gys = (a20 - a00) + 2.f * (a21 - a01) + (a22 - a02);

        float ang = atan2f(gys, gxs);
        if (ang < 0.f) ang += TWO_PI_F;
        int bin = (int)floorf(ang / STEP_F);
        bin = min(max(bin, 0), 7);
        int b8 = (bin + 2) & 7;

        int dy = c_dy[b8], dx = c_dx[b8];
        int step = dy * SPITCH + dx;
        float f = 0.f, w = 0.f;
#pragma unroll
        for (int r = 1; r <= 6; r++) {
            f = fmaxf(f, t0[-step * r]);
            w = fmaxf(w, t0[ step * r]);
        }
        float mn = fminf(f, w), mx = fmaxf(f, w);
        float ratio = mn / (mx + EPSV);
        float x0 = t0[0];
        float em = fminf(fmaxf(x0 * (1.f - ratio), 0.f), 1.f);

        size_t o = (size_t)b * HW + (size_t)(by + ly) * W + (bx + lx);
        emap[o] = em;
        if (binsf) binsf[o] = (float)b8;
        if (xnout) xnout[o] = x0;
    }
}

// ---------------- launch ----------------
extern "C" void kernel_launch(void* const* d_in, const int* in_sizes, int n_in,
                              void* d_out, int out_size) {
    const float* x = (const float*)d_in[0];
    float* out = (float*)d_out;
    const size_t N = (size_t)BATCH * HW;

    float* emap  = out;
    float* binsf = ((size_t)out_size >= 2 * N) ? out + N : nullptr;
    float* xnout = ((size_t)out_size >= 3 * N) ? out + 2 * N : nullptr;

    k_bounds<<<BATCH, 1024>>>(x);
    k_collect<<<dim3(64, BATCH), 256>>>(x);
    k_select<<<BATCH * 2, 256>>>();
    k_rescue<<<BATCH, 256>>>(x);

    dim3 gf(W / TS, H / TS, BATCH);
    k_fused<<<gf, 512>>>(x, emap, binsf, xnout);
}

// round 8
// speedup vs baseline: 1.9217x; 1.9217x over previous
#include <cuda_runtime.h>
#include <math.h>
#include <stdint.h>

#define BATCH 16
#define H 1024
#define W 1024
#define HW (H * W)
#define NB 4096
#define NSAMP 65536
#define TWO_PI_F 6.28318530717958647692f
#define STEP_F 0.78539816339744830962f
#define EPSV 1e-6f

// fractional global rank targets: 0.02*(HW-1)=20971.5, 0.98*(HW-1)=1027603.5
__constant__ int c_ranks[4] = {20971, 20972, 1027603, 1027604};
// sample-rank walk targets (NSAMP=65536): mean 1310.7 / 64225.3, margin ~9.5 sigma
__constant__ int c_wrank[4] = {968, 1653, 63883, 64567};

// ---------------- device scratch ----------------
__device__ unsigned g_qh[BATCH][2][NB];
__device__ unsigned g_below[BATCH][2];
__device__ float    g_slo[BATCH][2];
__device__ float    g_shi[BATCH][2];
__device__ float    g_sinv[BATCH][2];
__device__ float    g_sbw[BATCH][2];
__device__ int      g_merged[BATCH];
__device__ int      g_fail[BATCH];
__device__ float    g_lo[BATCH];
__device__ float    g_den[BATCH];
__device__ float    g_qval[BATCH][4];

__constant__ int c_dy[8] = {0, -1, -1, -1, 0, 1, 1, 1};
__constant__ int c_dx[8] = {1, 1, 0, -1, -1, -1, 0, 1};

__device__ __forceinline__ unsigned f2key(float f) {
    unsigned u = __float_as_uint(f);
    return (u & 0x80000000u) ? ~u : (u | 0x80000000u);
}
__device__ __forceinline__ float key2f(unsigned k) {
    unsigned u = (k & 0x80000000u) ? (k & 0x7fffffffu) : ~k;
    return __uint_as_float(u);
}
__device__ __forceinline__ int sample_idx(int i) {
    int chunk = i >> 6;                 // one 64-float run per row
    int off = (chunk * 7919) & 960;     // 64-aligned pseudo-random offset
    return (chunk << 10) + off + (i & 63);
}

// warp walk over histogram; returns bin, residual rank, and total count
__device__ __forceinline__ int warp_walk_tot(const unsigned* hist, int nb, int& rank, unsigned& total) {
    int lane = threadIdx.x & 31;
    int chunk = nb / 32;
    const unsigned* hc = hist + lane * chunk;
    unsigned s = 0;
    for (int j = 0; j < chunk; j++) s += hc[j];
    unsigned inc = s;
#pragma unroll
    for (int o = 1; o < 32; o <<= 1) {
        unsigned v = __shfl_up_sync(0xffffffffu, inc, o);
        if (lane >= o) inc += v;
    }
    total = __shfl_sync(0xffffffffu, inc, 31);
    unsigned ex = inc - s;
    unsigned ball = __ballot_sync(0xffffffffu, (int)ex <= rank);
    int sel = 31 - __clz(ball);
    int d = 0, r = rank;
    if (lane == sel) {
        r = rank - (int)ex;
        d = lane * chunk;
        for (int j = 0; j < chunk; j++) {
            unsigned c = hc[j];
            if (r < (int)c) { d = lane * chunk + j; break; }
            r -= (int)c;
        }
    }
    d = __shfl_sync(0xffffffffu, d, sel);
    r = __shfl_sync(0xffffffffu, r, sel);
    rank = r;
    return d;
}

// ---------------- sampled bounds + init (one block per batch) ----------------
__global__ __launch_bounds__(1024) void k_bounds(const float* __restrict__ x) {
    __shared__ unsigned h[8192];
    __shared__ float red[64];
    __shared__ int sb[4];
    __shared__ float s_mn, s_scale;
    int b = blockIdx.x;
    const float* xb = x + (size_t)b * HW;
    int tid = threadIdx.x;

    // zero this batch's value histograms + counters
    for (int i = tid; i < 2 * NB; i += 1024) (&g_qh[b][0][0])[i] = 0u;
    if (tid < 2) g_below[b][tid] = 0u;
    if (tid == 0) g_fail[b] = 0;

    // pass 1: sample min/max
    float mn = __int_as_float(0x7f800000), mx = -mn;
    for (int i = tid; i < NSAMP; i += 1024) {
        float v = xb[sample_idx(i)];
        mn = fminf(mn, v); mx = fmaxf(mx, v);
    }
#pragma unroll
    for (int o = 16; o > 0; o >>= 1) {
        mn = fminf(mn, __shfl_down_sync(0xffffffffu, mn, o));
        mx = fmaxf(mx, __shfl_down_sync(0xffffffffu, mx, o));
    }
    int w = tid >> 5;
    if ((tid & 31) == 0) { red[w] = mn; red[32 + w] = mx; }
    __syncthreads();
    if (tid == 0) {
        float m0 = red[0], m1 = red[32];
        for (int i = 1; i < 32; i++) { m0 = fminf(m0, red[i]); m1 = fmaxf(m1, red[32 + i]); }
        s_mn = m0;
        float span = m1 - m0;
        s_scale = (span > 1e-20f) ? 8192.0f / span : -1.0f;
    }
    for (int i = tid; i < 8192; i += 1024) h[i] = 0u;
    __syncthreads();
    float smn = s_mn, sscale = s_scale;
    if (sscale < 0.f) {  // degenerate data -> exact rescue
        if (tid == 0) {
            g_fail[b] = 1;
            float inf = __int_as_float(0x7f800000);
            g_slo[b][0] = inf; g_shi[b][0] = inf;
            g_slo[b][1] = inf; g_shi[b][1] = inf;
        }
        return;
    }
    float bw8 = 1.0f / sscale;

    // pass 2: sample value histogram
    for (int i = tid; i < NSAMP; i += 1024) {
        float v = xb[sample_idx(i)];
        int bin = (int)((v - smn) * sscale);
        atomicAdd(&h[min(max(bin, 0), 8191)], 1u);
    }
    __syncthreads();
    if (w < 4) {
        int r = c_wrank[w];
        unsigned tot;
        int d = warp_walk_tot(h, 8192, r, tot);
        if ((tid & 31) == 0) sb[w] = d;
    }
    __syncthreads();
    if (tid == 0) {
        float inf = __int_as_float(0x7f800000);
        float l0 = smn + (float)(sb[0] - 1) * bw8;
        float h0 = smn + (float)(sb[1] + 2) * bw8;
        float l1 = smn + (float)(sb[2] - 1) * bw8;
        float h1 = smn + (float)(sb[3] + 2) * bw8;
        int merged = (l1 <= h0);
        if (merged) { h0 = h1; l1 = inf; h1 = inf; }
        g_merged[b] = merged;
        g_slo[b][0] = l0; g_shi[b][0] = h0;
        g_sinv[b][0] = (float)NB / (h0 - l0);
        g_sbw[b][0] = (h0 - l0) / (float)NB;
        g_slo[b][1] = l1; g_shi[b][1] = h1;
        if (!merged) {
            g_sinv[b][1] = (float)NB / (h1 - l1);
            g_sbw[b][1] = (h1 - l1) / (float)NB;
        } else {
            g_sinv[b][1] = 0.f; g_sbw[b][1] = 0.f;
        }
    }
}

// ---------------- one full scan: below-counts + bracketed value histogram ----------------
__global__ __launch_bounds__(256) void k_qhist(const float* __restrict__ x) {
    int b = blockIdx.y;
    float l0 = g_slo[b][0], h0 = g_shi[b][0], inv0 = g_sinv[b][0];
    float l1 = g_slo[b][1], h1 = g_shi[b][1], inv1 = g_sinv[b][1];
    unsigned* hist0 = g_qh[b][0];
    unsigned* hist1 = g_qh[b][1];
    unsigned below0 = 0, below1 = 0;

    const float4* xb = (const float4*)(x + (size_t)b * HW);
    const int nvec = HW / 4;
    for (int i = blockIdx.x * blockDim.x + threadIdx.x; i < nvec; i += gridDim.x * blockDim.x) {
        float4 v4 = xb[i];
        float vs[4] = {v4.x, v4.y, v4.z, v4.w};
#pragma unroll
        for (int e = 0; e < 4; e++) {
            float v = vs[e];
            below0 += (v < l0);
            below1 += (v < l1);
            if (v >= l0 && v < h0) {
                int bin = (int)((v - l0) * inv0);
                atomicAdd(&hist0[min(bin, NB - 1)], 1u);
            } else if (v >= l1 && v < h1) {
                int bin = (int)((v - l1) * inv1);
                atomicAdd(&hist1[min(bin, NB - 1)], 1u);
            }
        }
    }
#pragma unroll
    for (int o = 16; o > 0; o >>= 1) {
        below0 += __shfl_down_sync(0xffffffffu, below0, o);
        below1 += __shfl_down_sync(0xffffffffu, below1, o);
    }
    if ((threadIdx.x & 31) == 0) {
        atomicAdd(&g_below[b][0], below0);
        atomicAdd(&g_below[b][1], below1);
    }
}

// ---------------- finalize: interpolating walk per quantile ----------------
__global__ void k_qfinal() {
    int b = blockIdx.x;
    if (g_fail[b]) return;
    __shared__ float qres[2];
    __shared__ int sfail;
    int tid = threadIdx.x;
    if (tid == 0) sfail = 0;
    __syncthreads();
    int w = tid >> 5;
    if (w < 2) {
        int slot = (w == 0) ? 0 : (g_merged[b] ? 0 : 1);
        int K = (w == 0) ? 20971 : 1027603;
        int r = K - (int)g_below[b][slot];
        unsigned total;
        if (r < 0) {
            if ((tid & 31) == 0) sfail = 1;
        } else {
            int rr = r;
            int d = warp_walk_tot(g_qh[b][slot], NB, rr, total);
            if ((tid & 31) == 0) {
                if ((unsigned)r >= total) sfail = 1;
                else {
                    unsigned n = g_qh[b][slot][d];
                    float q = g_slo[b][slot] +
                              ((float)d + ((float)rr + 1.0f) / (float)n) * g_sbw[b][slot];
                    qres[w] = q;
                }
            }
        }
    }
    __syncthreads();
    if (tid == 0) {
        if (sfail) g_fail[b] = 1;
        else { float lo = qres[0], hi = qres[1]; g_lo[b] = lo; g_den[b] = hi - lo + EPSV; }
    }
}

// ---------------- rescue: full exact per-batch select (gated; normally no-op) ----------------
__global__ void k_rescue(const float* __restrict__ x) {
    int b = blockIdx.x;
    if (!g_fail[b]) return;
    __shared__ unsigned h[8192];
    __shared__ int sbin[4], sd2[4], srnk[4];
    const float* xb = x + (size_t)b * HW;

    for (int i = threadIdx.x; i < 8192; i += blockDim.x) h[i] = 0u;
    __syncthreads();
    for (int i = threadIdx.x; i < HW; i += blockDim.x)
        atomicAdd(&h[f2key(xb[i]) >> 19], 1u);
    __syncthreads();
    int w = threadIdx.x >> 5;
    if (w < 4) {
        int r = c_ranks[w];
        unsigned tot;
        int d = warp_walk_tot(h, 8192, r, tot);
        if ((threadIdx.x & 31) == 0) { sbin[w] = d; srnk[w] = r; }
    }
    __syncthreads();
    for (int t = 0; t < 4; t++) {
        for (int i = threadIdx.x; i < 2048; i += blockDim.x) h[i] = 0u;
        __syncthreads();
        unsigned tb = (unsigned)sbin[t];
        for (int i = threadIdx.x; i < HW; i += blockDim.x) {
            unsigned k = f2key(xb[i]);
            if ((k >> 19) == tb) atomicAdd(&h[(k >> 8) & 2047u], 1u);
        }
        __syncthreads();
        if (w == 0) {
            int r = srnk[t];
            unsigned tot;
            int d = warp_walk_tot(h, 2048, r, tot);
            if ((threadIdx.x & 31) == 0) { sd2[t] = d; srnk[t] = r; }
        }
        __syncthreads();
    }
    for (int t = 0; t < 4; t++) {
        for (int i = threadIdx.x; i < 256; i += blockDim.x) h[i] = 0u;
        __syncthreads();
        unsigned pre = ((unsigned)sbin[t] << 11) | (unsigned)sd2[t];
        for (int i = threadIdx.x; i < HW; i += blockDim.x) {
            unsigned k = f2key(xb[i]);
            if ((k >> 8) == pre) atomicAdd(&h[k & 255u], 1u);
        }
        __syncthreads();
        if (w == 0) {
            int r = srnk[t];
            unsigned tot;
            int d = warp_walk_tot(h, 256, r, tot);
            if ((threadIdx.x & 31) == 0)
                g_qval[b][t] = key2f(((unsigned)sbin[t] << 19) | ((unsigned)sd2[t] << 8) | (unsigned)d);
        }
        __syncthreads();
    }
    if (threadIdx.x == 0) {
        float q0 = g_qval[b][0], q1 = g_qval[b][1];
        float q2 = g_qval[b][2], q3 = g_qval[b][3];
        float lo = q0 + 0.5f * (q1 - q0);
        float hi = q2 + 0.5f * (q3 - q2);
        g_lo[b] = lo;
        g_den[b] = hi - lo + EPSV;
    }
}

// ---------------- fused: normalize + sobel + atan2 + dir-max + end map (64x64) ----------------
#define TS 64
#define HALO 6
#define SW (TS + 2 * HALO)   // 76
#define SPITCH (SW + 1)      // 77

__global__ __launch_bounds__(512) void k_fused(const float* __restrict__ x,
                                               float* __restrict__ emap,
                                               float* __restrict__ binsf,
                                               float* __restrict__ xnout) {
    __shared__ float tile[SW * SPITCH];
    int b = blockIdx.z;
    int bx = blockIdx.x * TS, by = blockIdx.y * TS;
    const float* xb = x + (size_t)b * HW;
    int tid = threadIdx.x;
    int l64 = tid & 63;
    int grp = tid >> 6;   // 0..7

    float lo = g_lo[b];
    float den = g_den[b];

    bool interior = (bx >= HALO) && (bx + TS + HALO <= W) && (by >= HALO) && (by + TS + HALO <= H);
    if (interior) {
        const float* src = xb + (size_t)(by - HALO) * W + (bx - HALO);
        for (int r = grp; r < SW; r += 8) {
            const float* row = src + r * W;
            float* trow = &tile[r * SPITCH];
            for (int c = l64; c < SW; c += 64)
                trow[c] = fminf(fmaxf((row[c] - lo) / den, 0.f), 1.f);
        }
    } else {
        for (int r = grp; r < SW; r += 8) {
            int gy = by + r - HALO;
            float* trow = &tile[r * SPITCH];
            for (int c = l64; c < SW; c += 64) {
                int gx = bx + c - HALO;
                float v = 0.f;
                if ((unsigned)gy < H && (unsigned)gx < W)
                    v = fminf(fmaxf((xb[gy * W + gx] - lo) / den, 0.f), 1.f);
                trow[c] = v;
            }
        }
    }
    __syncthreads();

#pragma unroll
    for (int k = 0; k < 8; k++) {
        int ly = grp + k * 8;
        int ty = ly + HALO, tx = l64 + HALO;
        const float* t0 = &tile[ty * SPITCH + tx];

        float a00 = t0[-SPITCH - 1], a01 = t0[-SPITCH], a02 = t0[-SPITCH + 1];
        float a10 = t0[-1], a12 = t0[1];
        float a20 = t0[SPITCH - 1], a21 = t0[SPITCH], a22 = t0[SPITCH + 1];
        float gxs = (a02 - a00) + 2.f * (a12 - a10) + (a22 - a20);
        float gys = (a20 - a00) + 2.f * (a21 - a01) + (a22 - a02);

        float ang = atan2f(gys, gxs);
        if (ang < 0.f) ang += TWO_PI_F;
        int bin = (int)floorf(ang / STEP_F);
        bin = min(max(bin, 0), 7);
        int b8 = (bin + 2) & 7;

        int dy = c_dy[b8], dx = c_dx[b8];
        int step = dy * SPITCH + dx;
        float f = 0.f, w = 0.f;
#pragma unroll
        for (int r = 1; r <= 6; r++) {
            f = fmaxf(f, t0[-step * r]);
            w = fmaxf(w, t0[ step * r]);
        }
        float mn = fminf(f, w), mx = fmaxf(f, w);
        float ratio = mn / (mx + EPSV);
        float x0 = t0[0];
        float em = fminf(fmaxf(x0 * (1.f - ratio), 0.f), 1.f);

        size_t o = (size_t)b * HW + (size_t)(by + ly) * W + (bx + l64);
        __stcs(&emap[o], em);
        if (binsf) __stcs(&binsf[o], (float)b8);
        if (xnout) __stcs(&xnout[o], x0);
    }
}

// ---------------- launch ----------------
extern "C" void kernel_launch(void* const* d_in, const int* in_sizes, int n_in,
                              void* d_out, int out_size) {
    const float* x = (const float*)d_in[0];
    float* out = (float*)d_out;
    const size_t N = (size_t)BATCH * HW;

    float* emap  = out;
    float* binsf = ((size_t)out_size >= 2 * N) ? out + N : nullptr;
    float* xnout = ((size_t)out_size >= 3 * N) ? out + 2 * N : nullptr;

    k_bounds<<<BATCH, 1024>>>(x);
    k_qhist<<<dim3(64, BATCH), 256>>>(x);
    k_qfinal<<<BATCH, 64>>>();
    k_rescue<<<BATCH, 256>>>(x);

    dim3 gf(W / TS, H / TS, BATCH);
    k_fused<<<gf, 512>>>(x, emap, binsf, xnout);
}